// round 16
// baseline (speedup 1.0000x reference)
#include <cuda_runtime.h>
#include <math.h>
#include <stdint.h>

#define NTH   1024
#define CSIZE 4
typedef unsigned long long ull;

__device__ float g_xT[12 * 32 * 128 * 64];
__device__ float g_gi[(size_t)32 * 12 * 4 * 64 * 96];

#define WQ_OFF     0
#define SCR_OFF    12288
#define HT_OFF     29184
#define HL_OFF     37888
#define PB_OFF     40192
#define XW_OFF     46528
#define UE_OFF     48640
#define VB_OFF     48704
#define W2TS_OFF   48768
#define RN2B1_OFF  49824
#define W2SH_OFF   49856
#define W2RH_OFF   49888
#define RN2B2H_OFF 49920
#define GBIH_OFF   49924
#define GBHH_OFF   50308
#define OUTW_OFF   50692
#define OUTB_OFF   50948
#define SMEM_FLOATS 50950
#define SMEM_BYTES  (SMEM_FLOATS * 4)

#define STA_OFF    SCR_OFF
#define G1WSC_OFF  SCR_OFF
#define G1XT_OFF   (SCR_OFF + 8192)
#define WSC2_OFF   (SCR_OFF + 8192)
#define R1W1T      (PB_OFF + 0)
#define R1B1       (PB_OFF + 64)
#define R1W2S      (PB_OFF + 96)
#define R1W2R      (PB_OFF + 224)
#define R1B2       (PB_OFF + 352)
#define UE4_OFF    (PB_OFF + 384)
#define VB4_OFF    (PB_OFF + 640)

__device__ __forceinline__ uint32_t smem_u32(const void* p) {
    uint32_t a;
    asm("{ .reg .u64 t; cvta.to.shared.u64 t, %1; cvt.u32.u64 %0, t; }"
        : "=r"(a) : "l"(p));
    return a;
}
__device__ __forceinline__ uint32_t mapa_u32(uint32_t a, uint32_t r) {
    uint32_t o;
    asm("mapa.shared::cluster.u32 %0, %1, %2;" : "=r"(o) : "r"(a), "r"(r));
    return o;
}
__device__ __forceinline__ void stc_f32(uint32_t a, float v) {
    asm volatile("st.shared::cluster.f32 [%0], %1;" :: "r"(a), "f"(v) : "memory");
}
__device__ __forceinline__ void stc_v2(uint32_t a, float x, float y) {
    asm volatile("st.shared::cluster.v2.f32 [%0], {%1,%2};"
                 :: "r"(a), "f"(x), "f"(y) : "memory");
}
__device__ __forceinline__ uint32_t ctarank() {
    uint32_t r; asm("mov.u32 %0, %%cluster_ctarank;" : "=r"(r)); return r;
}
#define CLUSTER_SYNC() do {                                             \
    asm volatile("barrier.cluster.arrive.aligned;" ::: "memory");        \
    asm volatile("barrier.cluster.wait.aligned;"   ::: "memory");        \
} while (0)

__device__ __forceinline__ ull pack2(float lo, float hi) {
    ull r; asm("mov.b64 %0, {%1,%2};" : "=l"(r) : "f"(lo), "f"(hi)); return r;
}
__device__ __forceinline__ ull fma2(ull a, ull b, ull c) {
    ull d; asm("fma.rn.f32x2 %0, %1, %2, %3;" : "=l"(d) : "l"(a), "l"(b), "l"(c));
    return d;
}
__device__ __forceinline__ void unpack2(ull v, float& lo, float& hi) {
    asm("mov.b64 {%0,%1}, %2;" : "=f"(lo), "=f"(hi) : "l"(v));
}
__device__ __forceinline__ ull d2u(double d) { return (ull)__double_as_longlong(d); }
__device__ __forceinline__ float eluf(float x) { return x > 0.f ? x : __expf(x) - 1.f; }
__device__ __forceinline__ float fsig(float x) { return __fdividef(1.f, 1.f + __expf(-x)); }
__device__ __forceinline__ float ftanh(float x) {
    return 1.f - __fdividef(2.f, __expf(2.f * x) + 1.f);
}

__global__ void __launch_bounds__(NTH, 1) __cluster_dims__(CSIZE, 1, 1)
gatrnn_kernel(const float* __restrict__ inputs, const float* __restrict__ hidden,
              const float* __restrict__ rn1_W1, const float* __restrict__ rn1_b1,
              const float* __restrict__ rn1_W2, const float* __restrict__ rn1_b2,
              const float* __restrict__ rn2_W1, const float* __restrict__ rn2_b1,
              const float* __restrict__ rn2_W2, const float* __restrict__ rn2_b2,
              const float* __restrict__ gWih, const float* __restrict__ gWhh,
              const float* __restrict__ gbih, const float* __restrict__ gbhh,
              const float* __restrict__ outW, const float* __restrict__ outb,
              float* __restrict__ out) {
    extern __shared__ float sm[];
    const int tid = threadIdx.x, lane = tid & 31, wid = tid >> 5;
    const int rank = (int)ctarank();
    const int b = blockIdx.x / CSIZE;
    uint32_t sbase = smem_u32(sm);

    uint32_t pbc[3], pbo[3];
    {
        int c = 0;
        #pragma unroll
        for (int p = 0; p < 4; ++p)
            if (p != rank) {
                pbc[c] = mapa_u32(sbase, (uint32_t)p);
                pbo[c] = (uint32_t)(PB_OFF + (((rank - p + 4) & 3) - 1) * 2112) * 4u;
                ++c;
            }
    }

    // ---- prologue: weights + constants ----
    for (int i = tid; i < 12288; i += NTH) {
        int r = i >> 7, k = i & 127;
        int g = r >> 5, l = r & 31;
        sm[WQ_OFF + k * 96 + r] = gWih[(size_t)(g * 128 + 32 * rank + l) * 128 + k];
    }
    for (int i = tid; i < 8192; i += NTH) {
        int n = i >> 7, c = i & 127;
        sm[HT_OFF + c * 68 + n] = hidden[(size_t)b * 8192 + i];
    }
    for (int i = tid; i < 1024; i += NTH) {
        int dl = i >> 5, k = i & 31;
        sm[W2TS_OFF + dl * 33 + k] = rn2_W1[k * 128 + 32 * rank + dl];
    }
    if (tid < 32) sm[RN2B1_OFF + tid] = rn2_b1[tid];
    if (tid < 32) sm[W2SH_OFF + tid] = rn2_W2[rank * 64 + tid];
    if (tid < 32) sm[W2RH_OFF + tid] = rn2_W2[rank * 64 + 32 + tid];
    if (tid == 0) sm[RN2B2H_OFF] = rn2_b2[rank];
    for (int i = tid; i < 384; i += NTH) { sm[GBIH_OFF + i] = gbih[i]; sm[GBHH_OFF + i] = gbhh[i]; }
    for (int i = tid; i < 256; i += NTH) sm[OUTW_OFF + i] = outW[i];
    if (tid < 2) sm[OUTB_OFF + tid] = outb[tid];
    for (int i = tid; i < 64; i += NTH) { int d = i >> 5, k = i & 31; sm[R1W1T + i] = rn1_W1[k * 2 + d]; }
    if (tid < 32) sm[R1B1 + tid] = rn1_b1[tid];
    for (int i = tid; i < 128; i += NTH) {
        int h = i >> 5, k = i & 31;
        sm[R1W2S + i] = rn1_W2[h * 64 + k];
        sm[R1W2R + i] = rn1_W2[h * 64 + 32 + k];
    }
    if (tid < 4) sm[R1B2 + tid] = rn1_b2[tid];
    __syncthreads();

    // ---- GAT1: 3 tiles per CTA -> g_xT (compute on warps 0-15) ----
    #pragma unroll 1
    for (int q3 = 0; q3 < 3; ++q3) {
        const int tt = rank * 3 + q3;
        const float* xin = inputs + (((size_t)tt * 32 + b) << 7);
        #pragma unroll
        for (int it = 0; it < 2; ++it) {
            int o = it * NTH + tid;
            int n = o >> 5, k = o & 31;
            sm[XW_OFF + n * 33 + k] = sm[R1B1 + k]
                + xin[n * 2] * sm[R1W1T + k] + xin[n * 2 + 1] * sm[R1W1T + 32 + k];
        }
        __syncthreads();
        if (tid < 512) {
            int i = tid & 63, h = (tid >> 6) & 3, uv = tid >> 8;
            const float* w2 = sm + (uv == 0 ? R1W2S : R1W2R) + h * 32;
            const float* xr = sm + XW_OFF + i * 33;
            float acc = 0.f;
            #pragma unroll
            for (int k4 = 0; k4 < 8; ++k4) {
                float4 w = *(const float4*)(w2 + 4 * k4);
                acc = fmaf(w.x, xr[4 * k4],     acc);
                acc = fmaf(w.y, xr[4 * k4 + 1], acc);
                acc = fmaf(w.z, xr[4 * k4 + 2], acc);
                acc = fmaf(w.w, xr[4 * k4 + 3], acc);
            }
            if (uv == 0) sm[UE4_OFF + h * 64 + i] = acc;
            else         sm[VB4_OFF + h * 64 + i] = acc + sm[R1B2 + h];
        }
        __syncthreads();
        if (wid < 16) {
            float* wsc = sm + G1WSC_OFF + wid * 512;
            #pragma unroll 1
            for (int pass = 0; pass < 2; ++pass) {
                float e1[2][4], e2[2][4], s[2][4];
                #pragma unroll
                for (int jj = 0; jj < 2; ++jj) {
                    int j = wid * 4 + pass * 2 + jj;
                    #pragma unroll
                    for (int h = 0; h < 4; ++h) {
                        float vb = sm[VB4_OFF + h * 64 + j];
                        e1[jj][h] = __expf(eluf(sm[UE4_OFF + h * 64 + lane] + vb));
                        e2[jj][h] = (lane < 31)
                            ? __expf(eluf(sm[UE4_OFF + h * 64 + 32 + lane] + vb)) : 0.f;
                        s[jj][h] = e1[jj][h] + e2[jj][h];
                    }
                }
                #pragma unroll
                for (int off = 16; off; off >>= 1)
                    #pragma unroll
                    for (int jj = 0; jj < 2; ++jj)
                        #pragma unroll
                        for (int h = 0; h < 4; ++h)
                            s[jj][h] += __shfl_xor_sync(0xffffffffu, s[jj][h], off);
                #pragma unroll
                for (int jj = 0; jj < 2; ++jj) {
                    float i0 = __fdividef(1.f, s[jj][0]), i1 = __fdividef(1.f, s[jj][1]);
                    float i2 = __fdividef(1.f, s[jj][2]), i3 = __fdividef(1.f, s[jj][3]);
                    *(float4*)(wsc + jj * 256 + 4 * lane) =
                        make_float4(e1[jj][0] * i0, e1[jj][1] * i1, e1[jj][2] * i2, e1[jj][3] * i3);
                    if (lane < 31)
                        *(float4*)(wsc + jj * 256 + 128 + 4 * lane) =
                            make_float4(e2[jj][0] * i0, e2[jj][1] * i1, e2[jj][2] * i2, e2[jj][3] * i3);
                }
                __syncwarp();
                ull a[2][2];
                a[0][0] = a[0][1] = a[1][0] = a[1][1] = 0;
                #pragma unroll 7
                for (int i = 0; i < 63; ++i) {
                    float xv = sm[XW_OFF + i * 33 + lane];
                    ull xv2 = pack2(xv, xv);
                    double2 p0 = *(const double2*)(wsc + 4 * i);
                    double2 p1 = *(const double2*)(wsc + 256 + 4 * i);
                    a[0][0] = fma2(d2u(p0.x), xv2, a[0][0]);
                    a[0][1] = fma2(d2u(p0.y), xv2, a[0][1]);
                    a[1][0] = fma2(d2u(p1.x), xv2, a[1][0]);
                    a[1][1] = fma2(d2u(p1.y), xv2, a[1][1]);
                }
                #pragma unroll
                for (int jj = 0; jj < 2; ++jj) {
                    int j = wid * 4 + pass * 2 + jj;
                    if (j == 63) continue;
                    float v0, v1, v2, v3;
                    unpack2(a[jj][0], v0, v1);
                    unpack2(a[jj][1], v2, v3);
                    sm[G1XT_OFF + (0 * 32 + lane) * 68 + j] = eluf(v0);
                    sm[G1XT_OFF + (1 * 32 + lane) * 68 + j] = eluf(v1);
                    sm[G1XT_OFF + (2 * 32 + lane) * 68 + j] = eluf(v2);
                    sm[G1XT_OFF + (3 * 32 + lane) * 68 + j] = eluf(v3);
                }
                __syncwarp();
            }
        }
        if (tid < 128) sm[G1XT_OFF + tid * 68 + 63] = 0.f;
        __syncthreads();
        float* gdst = g_xT + ((size_t)tt * 32 + b) * 8192;
        for (int i = tid; i < 8192; i += NTH)
            gdst[i] = sm[G1XT_OFF + (i >> 6) * 68 + (i & 63)];
        __syncthreads();
    }
    __threadfence();
    CLUSTER_SYNC();

    // ---- gi GEMM: 6 rounds, 2 tiles, 16 warps each, 4 rows/warp ----
    #pragma unroll 1
    for (int r6 = 0; r6 < 6; ++r6) {
        {
            const float4* sA = (const float4*)(g_xT + ((size_t)r6 * 32 + b) * 8192);
            const float4* sB = (const float4*)(g_xT + ((size_t)(r6 + 6) * 32 + b) * 8192);
            float4* dA = (float4*)(sm + STA_OFF);
            float4* dB = (float4*)(sm + STA_OFF + 8192);
            for (int i = tid; i < 2048; i += NTH) { dA[i] = sA[i]; dB[i] = sB[i]; }
        }
        __syncthreads();
        {
            const bool ga = wid < 16;
            const int t = ga ? r6 : r6 + 6;
            const float* buf = sm + STA_OFF + (ga ? 0 : 8192);
            const int r0 = (wid & 15) * 4;
            ull ar[2], az[2], an[2];
            ar[0] = ar[1] = az[0] = az[1] = an[0] = an[1] = 0;
            #pragma unroll 2
            for (int k = 0; k < 128; ++k) {
                const float* wk = sm + WQ_OFF + k * 96;
                ull wr2 = pack2(wk[lane], wk[lane]);
                ull wz2 = pack2(wk[32 + lane], wk[32 + lane]);
                ull wn2 = pack2(wk[64 + lane], wk[64 + lane]);
                double2 v0 = *(const double2*)(buf + k * 64 + r0);
                ull p0 = d2u(v0.x), p1 = d2u(v0.y);
                ar[0] = fma2(p0, wr2, ar[0]); az[0] = fma2(p0, wz2, az[0]); an[0] = fma2(p0, wn2, an[0]);
                ar[1] = fma2(p1, wr2, ar[1]); az[1] = fma2(p1, wz2, az[1]); an[1] = fma2(p1, wn2, an[1]);
            }
            size_t gbase = ((size_t)(b * 12 + t) * 4 + rank) * 6144
                         + (size_t)r0 * 96 + lane;
            #pragma unroll
            for (int q = 0; q < 2; ++q) {
                float r0v, r1v, z0v, z1v, n0v, n1v;
                unpack2(ar[q], r0v, r1v);
                unpack2(az[q], z0v, z1v);
                unpack2(an[q], n0v, n1v);
                size_t o = gbase + (size_t)(2 * q) * 96;
                g_gi[o]           = r0v; g_gi[o + 32]      = z0v; g_gi[o + 64]      = n0v;
                g_gi[o + 96]      = r1v; g_gi[o + 96 + 32] = z1v; g_gi[o + 96 + 64] = n1v;
            }
        }
        __syncthreads();
    }

    // ---- overwrite WQ with Whh slice ----
    for (int i = tid; i < 12288; i += NTH) {
        int r = i >> 7, k = i & 127;
        int g = r >> 5, l = r & 31;
        sm[WQ_OFF + k * 96 + r] = gWhh[(size_t)(g * 128 + 32 * rank + l) * 128 + k];
    }
    __syncthreads();
    CLUSTER_SYNC();

    // ---- 12 recurrent steps ----
    #pragma unroll 1
    for (int t = 0; t < 12; ++t) {
        // GRU: h-part GEMM k-split (x: warps 0-15, h: 16-31), 4 rows/warp
        {
            const bool xp = wid < 16;
            const int r0 = (wid & 15) * 4;
            float gr[4], gz[4], gn_[4];
            if (xp) {
                const float* g = g_gi + ((size_t)(b * 12 + t) * 4 + rank) * 6144
                               + (size_t)r0 * 96 + lane;
                #pragma unroll
                for (int i = 0; i < 4; ++i) {
                    gr[i]  = g[i * 96];
                    gz[i]  = g[i * 96 + 32];
                    gn_[i] = g[i * 96 + 64];
                }
            }
            const float* wq  = sm + WQ_OFF + (xp ? 0 : 64 * 96);
            const float* act = sm + HT_OFF + (xp ? 0 : 64 * 68);
            ull ar[2], az[2], an[2];
            ar[0] = ar[1] = az[0] = az[1] = an[0] = an[1] = 0;
            #pragma unroll 2
            for (int k = 0; k < 64; ++k) {
                const float* wk = wq + k * 96;
                ull wr2 = pack2(wk[lane], wk[lane]);
                ull wz2 = pack2(wk[32 + lane], wk[32 + lane]);
                ull wn2 = pack2(wk[64 + lane], wk[64 + lane]);
                double2 v0 = *(const double2*)(act + k * 68 + r0);
                ull p0 = d2u(v0.x), p1 = d2u(v0.y);
                ar[0] = fma2(p0, wr2, ar[0]); az[0] = fma2(p0, wz2, az[0]); an[0] = fma2(p0, wn2, an[0]);
                ar[1] = fma2(p1, wr2, ar[1]); az[1] = fma2(p1, wz2, az[1]); an[1] = fma2(p1, wn2, an[1]);
            }
            if (!xp) {
                double* d = (double*)(sm + SCR_OFF + ((wid - 16) * 32 + lane) * 12);
                #pragma unroll
                for (int q = 0; q < 2; ++q) {
                    d[q]     = __longlong_as_double((long long)ar[q]);
                    d[2 + q] = __longlong_as_double((long long)az[q]);
                    d[4 + q] = __longlong_as_double((long long)an[q]);
                }
            }
            __syncthreads();
            if (xp) {
                const double* d = (const double*)(sm + SCR_OFF + (wid * 32 + lane) * 12);
                const int cg = rank * 32 + lane;
                float bir  = sm[GBIH_OFF + cg],       bhr = sm[GBHH_OFF + cg];
                float biz  = sm[GBIH_OFF + 128 + cg], bhz = sm[GBHH_OFF + 128 + cg];
                float bin_ = sm[GBIH_OFF + 256 + cg], bhn = sm[GBHH_OFF + 256 + cg];
                #pragma unroll
                for (int q = 0; q < 2; ++q) {
                    float ra0, ra1, za0, za1, na0, na1;
                    unpack2(ar[q], ra0, ra1);
                    unpack2(az[q], za0, za1);
                    unpack2(an[q], na0, na1);
                    float rb0, rb1, zb0, zb1, nb0, nb1;
                    unpack2((ull)__double_as_longlong(d[q]),     rb0, rb1);
                    unpack2((ull)__double_as_longlong(d[2 + q]), zb0, zb1);
                    unpack2((ull)__double_as_longlong(d[4 + q]), nb0, nb1);
                    int row = r0 + 2 * q;
                    float hold0 = sm[HT_OFF + cg * 68 + row];
                    float hold1 = sm[HT_OFF + cg * 68 + row + 1];
                    float rr0 = fsig(gr[2 * q] + ra0 + rb0 + bir + bhr);
                    float zz0 = fsig(gz[2 * q] + za0 + zb0 + biz + bhz);
                    float nn0 = ftanh(fmaf(rr0, na0 + nb0 + bhn, gn_[2 * q] + bin_));
                    sm[HL_OFF + row * 36 + lane] = fmaf(zz0, hold0 - nn0, nn0);
                    float rr1 = fsig(gr[2 * q + 1] + ra1 + rb1 + bir + bhr);
                    float zz1 = fsig(gz[2 * q + 1] + za1 + zb1 + biz + bhz);
                    float nn1 = ftanh(fmaf(rr1, na1 + nb1 + bhn, gn_[2 * q + 1] + bin_));
                    sm[HL_OFF + (row + 1) * 36 + lane] = fmaf(zz1, hold1 - nn1, nn1);
                }
            }
        }
        __syncthreads();

        // fc1 partials: 2 rows/warp; push to peers
        float own[2];
        {
            float wreg[32];
            #pragma unroll
            for (int dl = 0; dl < 32; ++dl) wreg[dl] = sm[W2TS_OFF + dl * 33 + lane];
            #pragma unroll
            for (int rpt = 0; rpt < 2; ++rpt) {
                int n = rpt * 32 + wid;
                const float* hr = sm + HL_OFF + n * 36;
                float acc = 0.f;
                #pragma unroll
                for (int q = 0; q < 8; ++q) {
                    float4 hv = *(const float4*)(hr + 4 * q);
                    acc = fmaf(hv.x, wreg[4 * q],     acc);
                    acc = fmaf(hv.y, wreg[4 * q + 1], acc);
                    acc = fmaf(hv.z, wreg[4 * q + 2], acc);
                    acc = fmaf(hv.w, wreg[4 * q + 3], acc);
                }
                own[rpt] = acc;
                uint32_t eb = (uint32_t)(n * 33 + lane) * 4u;
                stc_f32(pbc[0] + pbo[0] + eb, acc);
                stc_f32(pbc[1] + pbo[1] + eb, acc);
                stc_f32(pbc[2] + pbo[2] + eb, acc);
            }
        }
        CLUSTER_SYNC();

        {
            float b1v = sm[RN2B1_OFF + lane];
            #pragma unroll
            for (int rpt = 0; rpt < 2; ++rpt) {
                int e = (rpt * 32 + wid) * 33 + lane;
                sm[XW_OFF + e] = own[rpt] + b1v
                    + sm[PB_OFF + e] + sm[PB_OFF + 2112 + e]
                    + sm[PB_OFF + 4224 + e];
            }
        }
        __syncthreads();

        if (tid < 128) {
            int i = tid & 63, uv = tid >> 6;
            const float* w2 = sm + (uv ? W2RH_OFF : W2SH_OFF);
            const float* xr = sm + XW_OFF + i * 33;
            float acc = 0.f;
            #pragma unroll
            for (int k4 = 0; k4 < 8; ++k4) {
                float4 w = *(const float4*)(w2 + 4 * k4);
                acc = fmaf(w.x, xr[4 * k4],     acc);
                acc = fmaf(w.y, xr[4 * k4 + 1], acc);
                acc = fmaf(w.z, xr[4 * k4 + 2], acc);
                acc = fmaf(w.w, xr[4 * k4 + 3], acc);
            }
            if (uv == 0) sm[UE_OFF + i] = acc;
            else         sm[VB_OFF + i] = acc + sm[RN2B2H_OFF];
        }
        __syncthreads();

        // gat_c: 2 receivers/warp, wsc pitch-2, 1 fma2/sender
        {
            float* wsc = sm + WSC2_OFF + wid * 128;    // [64 i][2 j]
            const int j0 = 2 * wid;
            float e1[2], e2[2], s2[2];
            float ue1 = sm[UE_OFF + lane];
            float ue2 = (lane < 31) ? sm[UE_OFF + 32 + lane] : 0.f;
            #pragma unroll
            for (int q = 0; q < 2; ++q) {
                float vb = sm[VB_OFF + j0 + q];
                e1[q] = __expf(eluf(ue1 + vb));
                e2[q] = (lane < 31) ? __expf(eluf(ue2 + vb)) : 0.f;
                s2[q] = e1[q] + e2[q];
            }
            #pragma unroll
            for (int off = 16; off; off >>= 1)
                #pragma unroll
                for (int q = 0; q < 2; ++q)
                    s2[q] += __shfl_xor_sync(0xffffffffu, s2[q], off);
            float i0 = __fdividef(1.f, s2[0]), i1 = __fdividef(1.f, s2[1]);
            *(float2*)(wsc + 2 * lane) = make_float2(e1[0] * i0, e1[1] * i1);
            if (lane < 31)
                *(float2*)(wsc + 2 * (32 + lane)) = make_float2(e2[0] * i0, e2[1] * i1);
            __syncwarp();

            ull a01 = 0;
            #pragma unroll 9
            for (int i = 0; i < 63; ++i) {
                float xv = sm[XW_OFF + i * 33 + lane];
                ull xv2 = pack2(xv, xv);
                double p = *(const double*)(wsc + 2 * i);
                a01 = fma2(d2u(p), xv2, a01);
            }
            float v0, v1;
            unpack2(a01, v0, v1);
            v0 = eluf(v0); v1 = eluf(v1);
            if (wid == 31) v1 = 0.f;                  // j=63: no incoming edges
            int off = HT_OFF + (rank * 32 + lane) * 68 + j0;
            *(float2*)(sm + off) = make_float2(v0, v1);
            uint32_t bo = (uint32_t)off * 4u;
            stc_v2(pbc[0] + bo, v0, v1);
            stc_v2(pbc[1] + bo, v0, v1);
            stc_v2(pbc[2] + bo, v0, v1);
        }
        CLUSTER_SYNC();
    }

    // ---- output: own 16 nodes ----
    if (tid < 32) {
        int n = 16 * rank + (tid >> 1), d = tid & 1;
        float acc = sm[OUTB_OFF + d];
        #pragma unroll 4
        for (int c = 0; c < 128; ++c)
            acc = fmaf(sm[OUTW_OFF + d * 128 + c], sm[HT_OFF + c * 68 + n], acc);
        out[b * 128 + n * 2 + d] = acc;
    }
}

extern "C" void kernel_launch(void* const* d_in, const int* in_sizes, int n_in,
                              void* d_out, int out_size) {
    const float* inputs = (const float*)d_in[0];
    const float* hidden = (const float*)d_in[1];
    const float* rn1_W1 = (const float*)d_in[4];
    const float* rn1_b1 = (const float*)d_in[5];
    const float* rn1_W2 = (const float*)d_in[6];
    const float* rn1_b2 = (const float*)d_in[7];
    const float* rn2_W1 = (const float*)d_in[8];
    const float* rn2_b1 = (const float*)d_in[9];
    const float* rn2_W2 = (const float*)d_in[10];
    const float* rn2_b2 = (const float*)d_in[11];
    const float* gWih   = (const float*)d_in[12];
    const float* gWhh   = (const float*)d_in[13];
    const float* gbih   = (const float*)d_in[14];
    const float* gbhh   = (const float*)d_in[15];
    const float* outW   = (const float*)d_in[16];
    const float* outb   = (const float*)d_in[17];
    float* out = (float*)d_out;

    cudaFuncSetAttribute(gatrnn_kernel,
                         cudaFuncAttributeMaxDynamicSharedMemorySize, SMEM_BYTES);

    gatrnn_kernel<<<32 * CSIZE, NTH, SMEM_BYTES>>>(
        inputs, hidden, rn1_W1, rn1_b1, rn1_W2, rn1_b2,
        rn2_W1, rn2_b1, rn2_W2, rn2_b2, gWih, gWhh,
        gbih, gbhh, outW, outb, out);
}

// round 17
// speedup vs baseline: 1.2238x; 1.2238x over previous
#include <cuda_runtime.h>
#include <math.h>
#include <stdint.h>

#define NTH   512
#define CSIZE 4
typedef unsigned long long ull;

__device__ float g_xT[12 * 32 * 128 * 64];
__device__ float g_gi[(size_t)32 * 12 * 4 * 64 * 96];

#define WQ_OFF     0
#define SCR_OFF    12288
#define HT_OFF     29184
#define HL_OFF     37888
#define PB_OFF     40192
#define XW_OFF     46528
#define UE_OFF     48640
#define VB_OFF     48704
#define W2TS_OFF   48768
#define RN2B1_OFF  49824
#define W2SH_OFF   49856
#define W2RH_OFF   49888
#define RN2B2H_OFF 49920
#define GBIH_OFF   49924
#define GBHH_OFF   50308
#define OUTW_OFF   50692
#define OUTB_OFF   50948
#define SMEM_FLOATS 50950
#define SMEM_BYTES  (SMEM_FLOATS * 4)

#define STA_OFF    SCR_OFF
#define G1WSC_OFF  SCR_OFF
#define G1XT_OFF   (SCR_OFF + 8192)
#define WSC2_OFF   (SCR_OFF + 8192)
#define R1W1T      (PB_OFF + 0)
#define R1B1       (PB_OFF + 64)
#define R1W2S      (PB_OFF + 96)
#define R1W2R      (PB_OFF + 224)
#define R1B2       (PB_OFF + 352)
#define UE4_OFF    (PB_OFF + 384)
#define VB4_OFF    (PB_OFF + 640)

__device__ __forceinline__ uint32_t smem_u32(const void* p) {
    uint32_t a;
    asm("{ .reg .u64 t; cvta.to.shared.u64 t, %1; cvt.u32.u64 %0, t; }"
        : "=r"(a) : "l"(p));
    return a;
}
__device__ __forceinline__ uint32_t mapa_u32(uint32_t a, uint32_t r) {
    uint32_t o;
    asm("mapa.shared::cluster.u32 %0, %1, %2;" : "=r"(o) : "r"(a), "r"(r));
    return o;
}
__device__ __forceinline__ void stc_f32(uint32_t a, float v) {
    asm volatile("st.shared::cluster.f32 [%0], %1;" :: "r"(a), "f"(v) : "memory");
}
__device__ __forceinline__ void stc_v4(uint32_t a, float4 v) {
    asm volatile("st.shared::cluster.v4.f32 [%0], {%1,%2,%3,%4};"
                 :: "r"(a), "f"(v.x), "f"(v.y), "f"(v.z), "f"(v.w) : "memory");
}
__device__ __forceinline__ uint32_t ctarank() {
    uint32_t r; asm("mov.u32 %0, %%cluster_ctarank;" : "=r"(r)); return r;
}
#define CLUSTER_SYNC() do {                                             \
    asm volatile("barrier.cluster.arrive.aligned;" ::: "memory");        \
    asm volatile("barrier.cluster.wait.aligned;"   ::: "memory");        \
} while (0)

__device__ __forceinline__ ull pack2(float lo, float hi) {
    ull r; asm("mov.b64 %0, {%1,%2};" : "=l"(r) : "f"(lo), "f"(hi)); return r;
}
__device__ __forceinline__ ull fma2(ull a, ull b, ull c) {
    ull d; asm("fma.rn.f32x2 %0, %1, %2, %3;" : "=l"(d) : "l"(a), "l"(b), "l"(c));
    return d;
}
__device__ __forceinline__ void unpack2(ull v, float& lo, float& hi) {
    asm("mov.b64 {%0,%1}, %2;" : "=f"(lo), "=f"(hi) : "l"(v));
}
__device__ __forceinline__ ull d2u(double d) { return (ull)__double_as_longlong(d); }
__device__ __forceinline__ float eluf(float x) { return x > 0.f ? x : __expf(x) - 1.f; }
__device__ __forceinline__ float fsig(float x) { return __fdividef(1.f, 1.f + __expf(-x)); }
__device__ __forceinline__ float ftanh(float x) {
    return 1.f - __fdividef(2.f, __expf(2.f * x) + 1.f);
}

__global__ void __launch_bounds__(NTH, 1) __cluster_dims__(CSIZE, 1, 1)
gatrnn_kernel(const float* __restrict__ inputs, const float* __restrict__ hidden,
              const float* __restrict__ rn1_W1, const float* __restrict__ rn1_b1,
              const float* __restrict__ rn1_W2, const float* __restrict__ rn1_b2,
              const float* __restrict__ rn2_W1, const float* __restrict__ rn2_b1,
              const float* __restrict__ rn2_W2, const float* __restrict__ rn2_b2,
              const float* __restrict__ gWih, const float* __restrict__ gWhh,
              const float* __restrict__ gbih, const float* __restrict__ gbhh,
              const float* __restrict__ outW, const float* __restrict__ outb,
              float* __restrict__ out) {
    extern __shared__ float sm[];
    const int tid = threadIdx.x, lane = tid & 31, wid = tid >> 5;
    const int rank = (int)ctarank();
    const int b = blockIdx.x / CSIZE;
    uint32_t sbase = smem_u32(sm);

    uint32_t pbc[3], pbo[3];
    {
        int c = 0;
        #pragma unroll
        for (int p = 0; p < 4; ++p)
            if (p != rank) {
                pbc[c] = mapa_u32(sbase, (uint32_t)p);
                pbo[c] = (uint32_t)(PB_OFF + (((rank - p + 4) & 3) - 1) * 2112) * 4u;
                ++c;
            }
    }

    // ---- prologue: weights + constants ----
    for (int i = tid; i < 12288; i += NTH) {
        int r = i >> 7, k = i & 127;
        int g = r >> 5, l = r & 31;
        sm[WQ_OFF + k * 96 + r] = gWih[(size_t)(g * 128 + 32 * rank + l) * 128 + k];
    }
    for (int i = tid; i < 8192; i += NTH) {
        int n = i >> 7, c = i & 127;
        sm[HT_OFF + c * 68 + n] = hidden[(size_t)b * 8192 + i];
    }
    for (int i = tid; i < 1024; i += NTH) {
        int dl = i >> 5, k = i & 31;
        sm[W2TS_OFF + dl * 33 + k] = rn2_W1[k * 128 + 32 * rank + dl];
    }
    if (tid < 32) sm[RN2B1_OFF + tid] = rn2_b1[tid];
    if (tid < 32) sm[W2SH_OFF + tid] = rn2_W2[rank * 64 + tid];
    if (tid < 32) sm[W2RH_OFF + tid] = rn2_W2[rank * 64 + 32 + tid];
    if (tid == 0) sm[RN2B2H_OFF] = rn2_b2[rank];
    for (int i = tid; i < 384; i += NTH) { sm[GBIH_OFF + i] = gbih[i]; sm[GBHH_OFF + i] = gbhh[i]; }
    for (int i = tid; i < 256; i += NTH) sm[OUTW_OFF + i] = outW[i];
    if (tid < 2) sm[OUTB_OFF + tid] = outb[tid];
    for (int i = tid; i < 64; i += NTH) { int d = i >> 5, k = i & 31; sm[R1W1T + i] = rn1_W1[k * 2 + d]; }
    if (tid < 32) sm[R1B1 + tid] = rn1_b1[tid];
    for (int i = tid; i < 128; i += NTH) {
        int h = i >> 5, k = i & 31;
        sm[R1W2S + i] = rn1_W2[h * 64 + k];
        sm[R1W2R + i] = rn1_W2[h * 64 + 32 + k];
    }
    if (tid < 4) sm[R1B2 + tid] = rn1_b2[tid];
    __syncthreads();

    // ---- GAT1: 3 tiles per CTA -> g_xT ----
    #pragma unroll 1
    for (int q3 = 0; q3 < 3; ++q3) {
        const int tt = rank * 3 + q3;
        const float* xin = inputs + (((size_t)tt * 32 + b) << 7);
        #pragma unroll
        for (int it = 0; it < 4; ++it) {
            int o = it * NTH + tid;
            int n = o >> 5, k = o & 31;
            sm[XW_OFF + n * 33 + k] = sm[R1B1 + k]
                + xin[n * 2] * sm[R1W1T + k] + xin[n * 2 + 1] * sm[R1W1T + 32 + k];
        }
        __syncthreads();
        {
            int i = tid & 63, h = (tid >> 6) & 3, uv = tid >> 8;
            const float* w2 = sm + (uv == 0 ? R1W2S : R1W2R) + h * 32;
            const float* xr = sm + XW_OFF + i * 33;
            float acc = 0.f;
            #pragma unroll
            for (int k4 = 0; k4 < 8; ++k4) {
                float4 w = *(const float4*)(w2 + 4 * k4);
                acc = fmaf(w.x, xr[4 * k4],     acc);
                acc = fmaf(w.y, xr[4 * k4 + 1], acc);
                acc = fmaf(w.z, xr[4 * k4 + 2], acc);
                acc = fmaf(w.w, xr[4 * k4 + 3], acc);
            }
            if (uv == 0) sm[UE4_OFF + h * 64 + i] = acc;
            else         sm[VB4_OFF + h * 64 + i] = acc + sm[R1B2 + h];
        }
        __syncthreads();
        {
            float* wsc = sm + G1WSC_OFF + wid * 512;
            #pragma unroll 1
            for (int pass = 0; pass < 2; ++pass) {
                float e1[2][4], e2[2][4], s[2][4];
                #pragma unroll
                for (int jj = 0; jj < 2; ++jj) {
                    int j = wid * 4 + pass * 2 + jj;
                    #pragma unroll
                    for (int h = 0; h < 4; ++h) {
                        float vb = sm[VB4_OFF + h * 64 + j];
                        e1[jj][h] = __expf(eluf(sm[UE4_OFF + h * 64 + lane] + vb));
                        e2[jj][h] = (lane < 31)
                            ? __expf(eluf(sm[UE4_OFF + h * 64 + 32 + lane] + vb)) : 0.f;
                        s[jj][h] = e1[jj][h] + e2[jj][h];
                    }
                }
                #pragma unroll
                for (int off = 16; off; off >>= 1)
                    #pragma unroll
                    for (int jj = 0; jj < 2; ++jj)
                        #pragma unroll
                        for (int h = 0; h < 4; ++h)
                            s[jj][h] += __shfl_xor_sync(0xffffffffu, s[jj][h], off);
                #pragma unroll
                for (int jj = 0; jj < 2; ++jj) {
                    float i0 = __fdividef(1.f, s[jj][0]), i1 = __fdividef(1.f, s[jj][1]);
                    float i2 = __fdividef(1.f, s[jj][2]), i3 = __fdividef(1.f, s[jj][3]);
                    *(float4*)(wsc + jj * 256 + 4 * lane) =
                        make_float4(e1[jj][0] * i0, e1[jj][1] * i1, e1[jj][2] * i2, e1[jj][3] * i3);
                    if (lane < 31)
                        *(float4*)(wsc + jj * 256 + 128 + 4 * lane) =
                            make_float4(e2[jj][0] * i0, e2[jj][1] * i1, e2[jj][2] * i2, e2[jj][3] * i3);
                }
                __syncwarp();
                ull a[2][2];
                a[0][0] = a[0][1] = a[1][0] = a[1][1] = 0;
                #pragma unroll 7
                for (int i = 0; i < 63; ++i) {
                    float xv = sm[XW_OFF + i * 33 + lane];
                    ull xv2 = pack2(xv, xv);
                    double2 p0 = *(const double2*)(wsc + 4 * i);
                    double2 p1 = *(const double2*)(wsc + 256 + 4 * i);
                    a[0][0] = fma2(d2u(p0.x), xv2, a[0][0]);
                    a[0][1] = fma2(d2u(p0.y), xv2, a[0][1]);
                    a[1][0] = fma2(d2u(p1.x), xv2, a[1][0]);
                    a[1][1] = fma2(d2u(p1.y), xv2, a[1][1]);
                }
                #pragma unroll
                for (int jj = 0; jj < 2; ++jj) {
                    int j = wid * 4 + pass * 2 + jj;
                    if (j == 63) continue;
                    float v0, v1, v2, v3;
                    unpack2(a[jj][0], v0, v1);
                    unpack2(a[jj][1], v2, v3);
                    sm[G1XT_OFF + (0 * 32 + lane) * 68 + j] = eluf(v0);
                    sm[G1XT_OFF + (1 * 32 + lane) * 68 + j] = eluf(v1);
                    sm[G1XT_OFF + (2 * 32 + lane) * 68 + j] = eluf(v2);
                    sm[G1XT_OFF + (3 * 32 + lane) * 68 + j] = eluf(v3);
                }
                __syncwarp();
            }
        }
        if (tid < 128) sm[G1XT_OFF + tid * 68 + 63] = 0.f;
        __syncthreads();
        float* gdst = g_xT + ((size_t)tt * 32 + b) * 8192;
        for (int i = tid; i < 8192; i += NTH)
            gdst[i] = sm[G1XT_OFF + (i >> 6) * 68 + (i & 63)];
        __syncthreads();
    }
    __threadfence();
    CLUSTER_SYNC();

    // ---- gi GEMM: 6 rounds, both warp groups GEMM (tiles r and r+6) ----
    #pragma unroll 1
    for (int r6 = 0; r6 < 6; ++r6) {
        {
            const float4* sA = (const float4*)(g_xT + ((size_t)r6 * 32 + b) * 8192);
            const float4* sB = (const float4*)(g_xT + ((size_t)(r6 + 6) * 32 + b) * 8192);
            float4* dA = (float4*)(sm + STA_OFF);
            float4* dB = (float4*)(sm + STA_OFF + 8192);
            for (int i = tid; i < 2048; i += NTH) { dA[i] = sA[i]; dB[i] = sB[i]; }
        }
        __syncthreads();
        {
            const bool ga = wid < 8;
            const int t = ga ? r6 : r6 + 6;
            const float* buf = sm + STA_OFF + (ga ? 0 : 8192);
            const int r0 = (wid & 7) * 8;
            ull ar[4], az[4], an[4];
            #pragma unroll
            for (int q = 0; q < 4; ++q) { ar[q] = 0; az[q] = 0; an[q] = 0; }
            #pragma unroll 4
            for (int k = 0; k < 128; ++k) {
                const float* wk = sm + WQ_OFF + k * 96;
                ull wr2 = pack2(wk[lane], wk[lane]);
                ull wz2 = pack2(wk[32 + lane], wk[32 + lane]);
                ull wn2 = pack2(wk[64 + lane], wk[64 + lane]);
                double2 v0 = *(const double2*)(buf + k * 64 + r0);
                double2 v1 = *(const double2*)(buf + k * 64 + r0 + 4);
                ull p0 = d2u(v0.x), p1 = d2u(v0.y), p2 = d2u(v1.x), p3 = d2u(v1.y);
                ar[0] = fma2(p0, wr2, ar[0]); az[0] = fma2(p0, wz2, az[0]); an[0] = fma2(p0, wn2, an[0]);
                ar[1] = fma2(p1, wr2, ar[1]); az[1] = fma2(p1, wz2, az[1]); an[1] = fma2(p1, wn2, an[1]);
                ar[2] = fma2(p2, wr2, ar[2]); az[2] = fma2(p2, wz2, az[2]); an[2] = fma2(p2, wn2, an[2]);
                ar[3] = fma2(p3, wr2, ar[3]); az[3] = fma2(p3, wz2, az[3]); an[3] = fma2(p3, wn2, an[3]);
            }
            size_t gbase = ((size_t)(b * 12 + t) * 4 + rank) * 6144
                         + (size_t)r0 * 96 + lane;
            #pragma unroll
            for (int q = 0; q < 4; ++q) {
                float r0v, r1v, z0v, z1v, n0v, n1v;
                unpack2(ar[q], r0v, r1v);
                unpack2(az[q], z0v, z1v);
                unpack2(an[q], n0v, n1v);
                size_t o = gbase + (size_t)(2 * q) * 96;
                g_gi[o]           = r0v; g_gi[o + 32]      = z0v; g_gi[o + 64]      = n0v;
                g_gi[o + 96]      = r1v; g_gi[o + 96 + 32] = z1v; g_gi[o + 96 + 64] = n1v;
            }
        }
        __syncthreads();
    }

    // ---- overwrite WQ with Whh slice ----
    for (int i = tid; i < 12288; i += NTH) {
        int r = i >> 7, k = i & 127;
        int g = r >> 5, l = r & 31;
        sm[WQ_OFF + k * 96 + r] = gWhh[(size_t)(g * 128 + 32 * rank + l) * 128 + k];
    }
    __syncthreads();
    CLUSTER_SYNC();

    // loop-invariant hoists
    const float b1v = sm[RN2B1_OFF + lane];

    // ---- 12 recurrent steps ----
    #pragma unroll 1
    for (int t = 0; t < 12; ++t) {
        {
            const bool xp = wid < 8;
            const int r0 = (wid & 7) * 8;
            float gr[8], gz[8], gn_[8];
            if (xp) {
                const float* g = g_gi + ((size_t)(b * 12 + t) * 4 + rank) * 6144
                               + (size_t)r0 * 96 + lane;
                #pragma unroll
                for (int i = 0; i < 8; ++i) {
                    gr[i]  = g[i * 96];
                    gz[i]  = g[i * 96 + 32];
                    gn_[i] = g[i * 96 + 64];
                }
            }
            const float* wq  = sm + WQ_OFF + (xp ? 0 : 64 * 96);
            const float* act = sm + HT_OFF + (xp ? 0 : 64 * 68);
            ull ar[4], az[4], an[4];
            #pragma unroll
            for (int q = 0; q < 4; ++q) { ar[q] = 0; az[q] = 0; an[q] = 0; }
            #pragma unroll 4
            for (int k = 0; k < 64; ++k) {
                const float* wk = wq + k * 96;
                ull wr2 = pack2(wk[lane], wk[lane]);
                ull wz2 = pack2(wk[32 + lane], wk[32 + lane]);
                ull wn2 = pack2(wk[64 + lane], wk[64 + lane]);
                double2 v0 = *(const double2*)(act + k * 68 + r0);
                double2 v1 = *(const double2*)(act + k * 68 + r0 + 4);
                ull p0 = d2u(v0.x), p1 = d2u(v0.y), p2 = d2u(v1.x), p3 = d2u(v1.y);
                ar[0] = fma2(p0, wr2, ar[0]); az[0] = fma2(p0, wz2, az[0]); an[0] = fma2(p0, wn2, an[0]);
                ar[1] = fma2(p1, wr2, ar[1]); az[1] = fma2(p1, wz2, az[1]); an[1] = fma2(p1, wn2, an[1]);
                ar[2] = fma2(p2, wr2, ar[2]); az[2] = fma2(p2, wz2, az[2]); an[2] = fma2(p2, wn2, an[2]);
                ar[3] = fma2(p3, wr2, ar[3]); az[3] = fma2(p3, wz2, az[3]); an[3] = fma2(p3, wn2, an[3]);
            }
            if (!xp) {
                double* d = (double*)(sm + SCR_OFF + ((wid - 8) * 32 + lane) * 26);
                #pragma unroll
                for (int q = 0; q < 4; ++q) {
                    d[q]     = __longlong_as_double((long long)ar[q]);
                    d[4 + q] = __longlong_as_double((long long)az[q]);
                    d[8 + q] = __longlong_as_double((long long)an[q]);
                }
            }
            __syncthreads();
            if (xp) {
                const double* d = (const double*)(sm + SCR_OFF + (wid * 32 + lane) * 26);
                const int cg = rank * 32 + lane;
                float bir  = sm[GBIH_OFF + cg],       bhr = sm[GBHH_OFF + cg];
                float biz  = sm[GBIH_OFF + 128 + cg], bhz = sm[GBHH_OFF + 128 + cg];
                float bin_ = sm[GBIH_OFF + 256 + cg], bhn = sm[GBHH_OFF + 256 + cg];
                #pragma unroll
                for (int q = 0; q < 4; ++q) {
                    float ra0, ra1, za0, za1, na0, na1;
                    unpack2(ar[q], ra0, ra1);
                    unpack2(az[q], za0, za1);
                    unpack2(an[q], na0, na1);
                    float rb0, rb1, zb0, zb1, nb0, nb1;
                    unpack2((ull)__double_as_longlong(d[q]),     rb0, rb1);
                    unpack2((ull)__double_as_longlong(d[4 + q]), zb0, zb1);
                    unpack2((ull)__double_as_longlong(d[8 + q]), nb0, nb1);
                    int row = r0 + 2 * q;
                    float hold0 = sm[HT_OFF + cg * 68 + row];
                    float hold1 = sm[HT_OFF + cg * 68 + row + 1];
                    float rr0 = fsig(gr[2 * q] + ra0 + rb0 + bir + bhr);
                    float zz0 = fsig(gz[2 * q] + za0 + zb0 + biz + bhz);
                    float nn0 = ftanh(fmaf(rr0, na0 + nb0 + bhn, gn_[2 * q] + bin_));
                    sm[HL_OFF + row * 36 + lane] = fmaf(zz0, hold0 - nn0, nn0);
                    float rr1 = fsig(gr[2 * q + 1] + ra1 + rb1 + bir + bhr);
                    float zz1 = fsig(gz[2 * q + 1] + za1 + zb1 + biz + bhz);
                    float nn1 = ftanh(fmaf(rr1, na1 + nb1 + bhn, gn_[2 * q + 1] + bin_));
                    sm[HL_OFF + (row + 1) * 36 + lane] = fmaf(zz1, hold1 - nn1, nn1);
                }
            }
        }
        __syncthreads();

        // fc1 partials; push to peers
        float own[4];
        {
            float wreg[32];
            #pragma unroll
            for (int dl = 0; dl < 32; ++dl) wreg[dl] = sm[W2TS_OFF + dl * 33 + lane];
            #pragma unroll
            for (int rpt = 0; rpt < 4; ++rpt) {
                int n = rpt * 16 + wid;
                const float* hr = sm + HL_OFF + n * 36;
                float acc = 0.f;
                #pragma unroll
                for (int q = 0; q < 8; ++q) {
                    float4 hv = *(const float4*)(hr + 4 * q);
                    acc = fmaf(hv.x, wreg[4 * q],     acc);
                    acc = fmaf(hv.y, wreg[4 * q + 1], acc);
                    acc = fmaf(hv.z, wreg[4 * q + 2], acc);
                    acc = fmaf(hv.w, wreg[4 * q + 3], acc);
                }
                own[rpt] = acc;
                uint32_t eb = (uint32_t)(n * 33 + lane) * 4u;
                stc_f32(pbc[0] + pbo[0] + eb, acc);
                stc_f32(pbc[1] + pbo[1] + eb, acc);
                stc_f32(pbc[2] + pbo[2] + eb, acc);
            }
        }
        CLUSTER_SYNC();

        {
            #pragma unroll
            for (int rpt = 0; rpt < 4; ++rpt) {
                int e = (rpt * 16 + wid) * 33 + lane;
                sm[XW_OFF + e] = own[rpt] + b1v
                    + sm[PB_OFF + e] + sm[PB_OFF + 2112 + e]
                    + sm[PB_OFF + 4224 + e];
            }
        }
        __syncthreads();

        if (tid < 128) {
            int i = tid & 63, uv = tid >> 6;
            const float* w2 = sm + (uv ? W2RH_OFF : W2SH_OFF);
            const float* xr = sm + XW_OFF + i * 33;
            float acc = 0.f;
            #pragma unroll
            for (int k4 = 0; k4 < 8; ++k4) {
                float4 w = *(const float4*)(w2 + 4 * k4);
                acc = fmaf(w.x, xr[4 * k4],     acc);
                acc = fmaf(w.y, xr[4 * k4 + 1], acc);
                acc = fmaf(w.z, xr[4 * k4 + 2], acc);
                acc = fmaf(w.w, xr[4 * k4 + 3], acc);
            }
            if (uv == 0) sm[UE_OFF + i] = acc;
            else         sm[VB_OFF + i] = acc + sm[RN2B2H_OFF];
        }
        __syncthreads();

        {
            float* wsc = sm + WSC2_OFF + wid * 256;
            const int j0 = 4 * wid;
            float e1[4], e2[4], s4[4];
            float ue1 = sm[UE_OFF + lane];
            float ue2 = (lane < 31) ? sm[UE_OFF + 32 + lane] : 0.f;
            #pragma unroll
            for (int q = 0; q < 4; ++q) {
                float vb = sm[VB_OFF + j0 + q];
                e1[q] = __expf(eluf(ue1 + vb));
                e2[q] = (lane < 31) ? __expf(eluf(ue2 + vb)) : 0.f;
                s4[q] = e1[q] + e2[q];
            }
            #pragma unroll
            for (int off = 16; off; off >>= 1)
                #pragma unroll
                for (int q = 0; q < 4; ++q)
                    s4[q] += __shfl_xor_sync(0xffffffffu, s4[q], off);
            float i0 = __fdividef(1.f, s4[0]), i1 = __fdividef(1.f, s4[1]);
            float i2 = __fdividef(1.f, s4[2]), i3 = __fdividef(1.f, s4[3]);
            *(float4*)(wsc + 4 * lane) =
                make_float4(e1[0] * i0, e1[1] * i1, e1[2] * i2, e1[3] * i3);
            if (lane < 31)
                *(float4*)(wsc + 4 * (32 + lane)) =
                    make_float4(e2[0] * i0, e2[1] * i1, e2[2] * i2, e2[3] * i3);
            __syncwarp();

            ull a01 = 0, a23 = 0;
            #pragma unroll 9
            for (int i = 0; i < 63; ++i) {
                float xv = sm[XW_OFF + i * 33 + lane];
                ull xv2 = pack2(xv, xv);
                double2 p = *(const double2*)(wsc + 4 * i);
                a01 = fma2(d2u(p.x), xv2, a01);
                a23 = fma2(d2u(p.y), xv2, a23);
            }
            float v0, v1, v2, v3;
            unpack2(a01, v0, v1);
            unpack2(a23, v2, v3);
            v0 = eluf(v0); v1 = eluf(v1); v2 = eluf(v2); v3 = eluf(v3);
            if (wid == 15) v3 = 0.f;
            float4 res = make_float4(v0, v1, v2, v3);
            int off = HT_OFF + (rank * 32 + lane) * 68 + j0;
            *(float4*)(sm + off) = res;
            uint32_t bo = (uint32_t)off * 4u;
            stc_v4(pbc[0] + bo, res);
            stc_v4(pbc[1] + bo, res);
            stc_v4(pbc[2] + bo, res);
        }
        CLUSTER_SYNC();
    }

    // ---- output: own 16 nodes ----
    if (tid < 32) {
        int n = 16 * rank + (tid >> 1), d = tid & 1;
        float acc = sm[OUTB_OFF + d];
        #pragma unroll 4
        for (int c = 0; c < 128; ++c)
            acc = fmaf(sm[OUTW_OFF + d * 128 + c], sm[HT_OFF + c * 68 + n], acc);
        out[b * 128 + n * 2 + d] = acc;
    }
}

extern "C" void kernel_launch(void* const* d_in, const int* in_sizes, int n_in,
                              void* d_out, int out_size) {
    const float* inputs = (const float*)d_in[0];
    const float* hidden = (const float*)d_in[1];
    const float* rn1_W1 = (const float*)d_in[4];
    const float* rn1_b1 = (const float*)d_in[5];
    const float* rn1_W2 = (const float*)d_in[6];
    const float* rn1_b2 = (const float*)d_in[7];
    const float* rn2_W1 = (const float*)d_in[8];
    const float* rn2_b1 = (const float*)d_in[9];
    const float* rn2_W2 = (const float*)d_in[10];
    const float* rn2_b2 = (const float*)d_in[11];
    const float* gWih   = (const float*)d_in[12];
    const float* gWhh   = (const float*)d_in[13];
    const float* gbih   = (const float*)d_in[14];
    const float* gbhh   = (const float*)d_in[15];
    const float* outW   = (const float*)d_in[16];
    const float* outb   = (const float*)d_in[17];
    float* out = (float*)d_out;

    cudaFuncSetAttribute(gatrnn_kernel,
                         cudaFuncAttributeMaxDynamicSharedMemorySize, SMEM_BYTES);

    gatrnn_kernel<<<32 * CSIZE, NTH, SMEM_BYTES>>>(
        inputs, hidden, rn1_W1, rn1_b1, rn1_W2, rn1_b2,
        rn2_W1, rn2_b1, rn2_W2, rn2_b2, gWih, gWhh,
        gbih, gbhh, outW, outb, out);
}